// round 1
// baseline (speedup 1.0000x reference)
#include <cuda_runtime.h>
#include <cuda_bf16.h>
#include <math.h>

// Problem constants
#define BB 2
#define SS 2048
#define EE 2048
#define HH_ 16
#define DD 128          // head dim (== RD, whole head rotates)
#define E3 (3*EE)

// Scratch (allocation-free rule: __device__ globals)
__device__ float g_qkv[(long)BB*SS*E3];        //  96 MB
__device__ float g_sc [(long)BB*HH_*SS*SS];    // 512 MB (scores, then probs in-place)
__device__ float g_ctx[(long)BB*SS*EE];        //  32 MB

// ---------------------------------------------------------------------------
// Generic SGEMM:  C[m,n] = sum_k A[m,k] * (TRANSB ? B[n,k] : B[k,n]) (+bias[n])
// 128x128 block tile, BK=16, 256 threads, 8x8 per thread.
// CAUSAL: 0 = none, 1 = skip tiles fully above diagonal (scores),
//         2 = limit K to m0+BM (P@V: probs are zero beyond the diagonal tile)
// Batched via blockIdx.z decomposed as z = zb*HH + zh with per-axis strides.
// ---------------------------------------------------------------------------
#define BM 128
#define BN 128
#define BK 16

template<bool TRANSB, bool BIAS, int CAUSAL>
__global__ __launch_bounds__(256)
void gemm_k(const float* __restrict__ gA, const float* __restrict__ gB,
            float* __restrict__ gC, const float* __restrict__ bias,
            int M, int N, int K, int lda, int ldb, int ldc,
            long sAb, long sAh, long sBb, long sBh, long sCb, long sCh, int HHd)
{
    int z  = blockIdx.z;
    int zb = z / HHd, zh = z % HHd;
    const float* A = gA + zb*sAb + zh*sAh;
    const float* Bp = gB + zb*sBb + zh*sBh;
    float*       C = gC + zb*sCb + zh*sCh;

    int m0 = blockIdx.y * BM;
    int n0 = blockIdx.x * BN;
    if (CAUSAL == 1 && n0 > m0 + BM - 1) return;     // fully-masked tile
    int Kend = (CAUSAL == 2) ? min(K, m0 + BM) : K;

    __shared__ float As[BK][BM];
    __shared__ float Bs[BK][BN];

    int tid = threadIdx.x;
    int tx = tid & 15, ty = tid >> 4;

    float acc[8][8];
    #pragma unroll
    for (int i = 0; i < 8; i++)
        #pragma unroll
        for (int j = 0; j < 8; j++) acc[i][j] = 0.f;

    for (int k0 = 0; k0 < Kend; k0 += BK) {
        // ---- load A tile (128 rows x 16 k), store transposed As[k][m]
        {
            int row = tid >> 2;
            int c4  = (tid & 3) * 4;
            #pragma unroll
            for (int p = 0; p < 2; p++) {
                int r = row + p*64;
                float4 v = *(const float4*)(A + (long)(m0 + r)*lda + k0 + c4);
                As[c4+0][r] = v.x; As[c4+1][r] = v.y;
                As[c4+2][r] = v.z; As[c4+3][r] = v.w;
            }
        }
        // ---- load B tile
        if (TRANSB) {
            int row = tid >> 2;
            int c4  = (tid & 3) * 4;
            #pragma unroll
            for (int p = 0; p < 2; p++) {
                int r = row + p*64;
                float4 v = *(const float4*)(Bp + (long)(n0 + r)*ldb + k0 + c4);
                Bs[c4+0][r] = v.x; Bs[c4+1][r] = v.y;
                Bs[c4+2][r] = v.z; Bs[c4+3][r] = v.w;
            }
        } else {
            #pragma unroll
            for (int p = 0; p < 2; p++) {
                int idx = tid + p*256;            // 0..511
                int kr  = idx >> 5;               // 0..15
                int c4  = (idx & 31) * 4;
                float4 v = *(const float4*)(Bp + (long)(k0 + kr)*ldb + n0 + c4);
                *(float4*)&Bs[kr][c4] = v;
            }
        }
        __syncthreads();

        #pragma unroll
        for (int kk = 0; kk < BK; kk++) {
            float a[8], b[8];
            *(float4*)&a[0] = *(const float4*)&As[kk][ty*8];
            *(float4*)&a[4] = *(const float4*)&As[kk][ty*8+4];
            *(float4*)&b[0] = *(const float4*)&Bs[kk][tx*8];
            *(float4*)&b[4] = *(const float4*)&Bs[kk][tx*8+4];
            #pragma unroll
            for (int i = 0; i < 8; i++)
                #pragma unroll
                for (int j = 0; j < 8; j++)
                    acc[i][j] = fmaf(a[i], b[j], acc[i][j]);
        }
        __syncthreads();
    }

    float bv[8];
    #pragma unroll
    for (int j = 0; j < 8; j++) bv[j] = BIAS ? bias[n0 + tx*8 + j] : 0.f;

    #pragma unroll
    for (int i = 0; i < 8; i++) {
        long cro = (long)(m0 + ty*8 + i)*ldc + n0 + tx*8;
        float4 s0, s1;
        s0.x = acc[i][0]+bv[0]; s0.y = acc[i][1]+bv[1];
        s0.z = acc[i][2]+bv[2]; s0.w = acc[i][3]+bv[3];
        s1.x = acc[i][4]+bv[4]; s1.y = acc[i][5]+bv[5];
        s1.z = acc[i][6]+bv[6]; s1.w = acc[i][7]+bv[7];
        *(float4*)(C + cro)     = s0;
        *(float4*)(C + cro + 4) = s1;
    }
}

// ---------------------------------------------------------------------------
// RoPE applied in-place to q and k inside g_qkv. One thread per (b,s,h,j<64).
// ---------------------------------------------------------------------------
__global__ __launch_bounds__(256)
void rope_k(float* __restrict__ qkv)
{
    long t = (long)blockIdx.x * blockDim.x + threadIdx.x;   // < B*S*H*64
    int j = (int)(t & 63);
    int h = (int)((t >> 6) & (HH_-1));
    long bs = t >> 10;                                      // b*S + s
    int s = (int)(bs & (SS-1));

    // mirror fp32 reference: inv_freq = 10000^-(2j/128)
    float inv = powf(10000.f, -((float)(2*j)) * (1.f/128.f));
    float fr  = (float)s * inv;
    float c, sn;
    sincosf(fr, &sn, &c);

    float* q = qkv + bs*(long)E3 + (long)h*DD;
    float q1 = q[j], q2 = q[j+64];
    q[j]    = q1*c - q2*sn;
    q[j+64] = q1*sn + q2*c;

    float* k = q + EE;
    float k1 = k[j], k2 = k[j+64];
    k[j]    = k1*c - k2*sn;
    k[j+64] = k1*sn + k2*c;
}

// ---------------------------------------------------------------------------
// Causal softmax over one row s of scores[z][s][:]; writes probs in place,
// zeros the masked tail so P@V can run dense tiles.
// ---------------------------------------------------------------------------
__global__ __launch_bounds__(256)
void softmax_k(float* __restrict__ p, float scale)
{
    const int S = SS;
    int s = blockIdx.x;
    long base = (long)blockIdx.y * S * S + (long)s * S;
    int n = s + 1;
    int tid = threadIdx.x;

    __shared__ float red[256];
    float ev[8];
    int cnt = 0;
    float mx = -3.4e38f;
    for (int i = tid; i < n; i += 256) {
        float v = p[base + i] * scale;
        ev[cnt++] = v;
        mx = fmaxf(mx, v);
    }
    red[tid] = mx; __syncthreads();
    for (int off = 128; off; off >>= 1) {
        if (tid < off) red[tid] = fmaxf(red[tid], red[tid + off]);
        __syncthreads();
    }
    mx = red[0]; __syncthreads();

    float sum = 0.f;
    for (int c = 0; c < cnt; c++) { ev[c] = expf(ev[c] - mx); sum += ev[c]; }
    red[tid] = sum; __syncthreads();
    for (int off = 128; off; off >>= 1) {
        if (tid < off) red[tid] += red[tid + off];
        __syncthreads();
    }
    float invs = 1.f / red[0];

    cnt = 0;
    for (int i = tid; i < n; i += 256) p[base + i] = ev[cnt++] * invs;
    for (int i = n + tid; i < S; i += 256) p[base + i] = 0.f;
}

// ---------------------------------------------------------------------------
extern "C" void kernel_launch(void* const* d_in, const int* in_sizes, int n_in,
                              void* d_out, int out_size)
{
    const float* x      = (const float*)d_in[0];
    const float* wqkv_w = (const float*)d_in[1];
    const float* wqkv_b = (const float*)d_in[2];
    const float* out_w  = (const float*)d_in[3];
    const float* out_b  = (const float*)d_in[4];
    float*       out    = (float*)d_out;

    float *qkv, *sc, *ctx;
    cudaGetSymbolAddress((void**)&qkv, g_qkv);
    cudaGetSymbolAddress((void**)&sc,  g_sc);
    cudaGetSymbolAddress((void**)&ctx, g_ctx);

    const int Mx = BB*SS;            // 4096
    const long sQKVb = (long)SS*E3;  // per-b stride in qkv
    const long sSCb  = (long)HH_*SS*SS;
    const long sSCh  = (long)SS*SS;

    // 1) QKV projection: [4096,2048] @ [6144,2048]^T + bias
    {
        dim3 g(E3/BN, Mx/BM, 1);
        gemm_k<true,true,0><<<g,256>>>(x, wqkv_w, qkv, wqkv_b,
            Mx, E3, EE, EE, EE, E3, 0,0,0,0,0,0, 1);
    }
    // 2) RoPE in place on q,k
    {
        long total = (long)BB*SS*HH_*64;
        rope_k<<<(unsigned)(total/256), 256>>>(qkv);
    }
    // 3) scores[z] = q @ k^T  (batched over z=b*H+h, causal tile skip)
    {
        dim3 g(SS/BN, SS/BM, BB*HH_);
        gemm_k<true,false,1><<<g,256>>>(qkv, qkv + EE, sc, nullptr,
            SS, SS, DD, E3, E3, SS,
            sQKVb, DD, sQKVb, DD, sSCb, sSCh, HH_);
    }
    // 4) causal softmax (scale folded in)
    {
        float scale = 1.f / sqrtf((float)DD);
        softmax_k<<<dim3(SS, BB*HH_), 256>>>(sc, scale);
    }
    // 5) ctx[z] = probs @ v  (NN, K limited by causality)
    {
        dim3 g(DD/BN, SS/BM, BB*HH_);
        gemm_k<false,false,2><<<g,256>>>(sc, qkv + 2*EE, ctx, nullptr,
            SS, DD, SS, SS, E3, EE,
            sSCb, sSCh, sQKVb, DD, (long)SS*EE, DD, HH_);
    }
    // 6) output projection + bias
    {
        dim3 g(EE/BN, Mx/BM, 1);
        gemm_k<true,true,0><<<g,256>>>(ctx, out_w, out, out_b,
            Mx, EE, EE, EE, EE, EE, 0,0,0,0,0,0, 1);
    }
}

// round 3
// speedup vs baseline: 2.5154x; 2.5154x over previous
#include <cuda_runtime.h>
#include <math.h>
#include <cstdint>

// Problem constants
#define BB 2
#define SS 2048
#define EE 2048
#define HH_ 16
#define DD 128
#define E3 (3*EE)

// Scratch (allocation-free rule: __device__ globals)
__device__ float g_qkv[(long)BB*SS*E3];        //  96 MB
__device__ float g_sc [(long)BB*HH_*SS*SS];    // 512 MB
__device__ float g_ctx[(long)BB*SS*EE];        //  32 MB

// ---------------------------------------------------------------------------
// tf32 mma.sync GEMM: C[m,n] = sum_k A[m,k] * (TRANSB ? B[n,k] : B[k,n]) (+bias)
// 128x128 tile, BK=32, 256 threads (8 warps, 2x4), 64x32 per warp.
// Smem: K-major, row stride 36 floats (conflict-free for m16n8k8 fragments).
// ---------------------------------------------------------------------------
#define BM 128
#define BN 128
#define BKT 32
#define LDS_ 36
#define TILE_U (128*LDS_)          // 4608 u32 per matrix tile
#define BUF_U  (2*TILE_U)          // A+B per buffer
#define SMEM_SZ (2*BUF_U*4)        // 73728 bytes (double buffered)

__device__ __forceinline__ uint32_t f2tf(float f) {
    uint32_t r; asm("cvt.rna.tf32.f32 %0, %1;" : "=r"(r) : "f"(f)); return r;
}
__device__ __forceinline__ void mma8(float* d, const uint32_t* a, const uint32_t* b) {
    asm volatile("mma.sync.aligned.m16n8k8.row.col.f32.tf32.tf32.f32 "
        "{%0,%1,%2,%3}, {%4,%5,%6,%7}, {%8,%9}, {%0,%1,%2,%3};"
        : "+f"(d[0]), "+f"(d[1]), "+f"(d[2]), "+f"(d[3])
        : "r"(a[0]), "r"(a[1]), "r"(a[2]), "r"(a[3]), "r"(b[0]), "r"(b[1]));
}

template<bool TRANSB, bool BIAS, int CAUSAL>
__global__ __launch_bounds__(256)
void tgemm(const float* __restrict__ gA, const float* __restrict__ gB,
           float* __restrict__ gC, const float* __restrict__ bias,
           int M, int N, int K, int lda, int ldb, int ldc,
           long sAb, long sAh, long sBb, long sBh, long sCb, long sCh, int HHd)
{
    extern __shared__ uint32_t smu[];
    int z = blockIdx.z, zb = z / HHd, zh = z % HHd;
    const float* A = gA + zb*sAb + zh*sAh;
    const float* B = gB + zb*sBb + zh*sBh;
    float*       C = gC + zb*sCb + zh*sCh;

    int m0 = blockIdx.y * BM;
    int n0 = blockIdx.x * BN;
    if (CAUSAL == 1 && n0 > m0 + BM - 1) return;
    int Kend = (CAUSAL == 2) ? min(K, m0 + BM) : K;
    int niter = Kend / BKT;

    int tid  = threadIdx.x;
    int wid  = tid >> 5;
    int lane = tid & 31;
    int wm = wid & 1;          // 0..1 : 64-row slab
    int wn = wid >> 1;         // 0..3 : 32-col slab
    int gq = lane >> 2;        // groupID 0..7
    int tg = lane & 3;         // thread-in-group 0..3

    float acc[4][4][4];
    #pragma unroll
    for (int mt = 0; mt < 4; mt++)
        #pragma unroll
        for (int nt = 0; nt < 4; nt++)
            #pragma unroll
            for (int r = 0; r < 4; r++) acc[mt][nt][r] = 0.f;

    float4 rA[4], rB[4];

    // --- global loads into regs for K-slice k0 ---
    auto loadA = [&](int k0) {
        const float* Ab = A + (long)m0 * lda + k0;
        #pragma unroll
        for (int p = 0; p < 4; p++) {
            int idx = p * 256 + tid;
            int row = idx >> 3, c4 = (idx & 7) << 2;
            rA[p] = *(const float4*)(Ab + (long)row * lda + c4);
        }
    };
    auto loadB = [&](int k0) {
        if (TRANSB) {
            const float* Bb = B + (long)n0 * ldb + k0;
            #pragma unroll
            for (int p = 0; p < 4; p++) {
                int idx = p * 256 + tid;
                int row = idx >> 3, c4 = (idx & 7) << 2;
                rB[p] = *(const float4*)(Bb + (long)row * ldb + c4);
            }
        } else {
            const float* Bb = B + (long)k0 * ldb + n0;
            #pragma unroll
            for (int p = 0; p < 4; p++) {
                int idx = p * 256 + tid;
                int kr = idx >> 5, c4 = (idx & 31) << 2;
                rB[p] = *(const float4*)(Bb + (long)kr * ldb + c4);
            }
        }
    };
    // --- convert + store regs into smem buffer ---
    auto store = [&](int buf) {
        uint32_t* As = smu + buf * BUF_U;
        uint32_t* Bs = As + TILE_U;
        #pragma unroll
        for (int p = 0; p < 4; p++) {
            int idx = p * 256 + tid;
            int row = idx >> 3, c4 = (idx & 7) << 2;
            uint32_t* d = As + row * LDS_ + c4;
            d[0] = f2tf(rA[p].x); d[1] = f2tf(rA[p].y);
            d[2] = f2tf(rA[p].z); d[3] = f2tf(rA[p].w);
        }
        if (TRANSB) {
            #pragma unroll
            for (int p = 0; p < 4; p++) {
                int idx = p * 256 + tid;
                int row = idx >> 3, c4 = (idx & 7) << 2;
                uint32_t* d = Bs + row * LDS_ + c4;
                d[0] = f2tf(rB[p].x); d[1] = f2tf(rB[p].y);
                d[2] = f2tf(rB[p].z); d[3] = f2tf(rB[p].w);
            }
        } else {
            #pragma unroll
            for (int p = 0; p < 4; p++) {
                int idx = p * 256 + tid;
                int kr = idx >> 5, c4 = (idx & 31) << 2;
                Bs[(c4+0) * LDS_ + kr] = f2tf(rB[p].x);
                Bs[(c4+1) * LDS_ + kr] = f2tf(rB[p].y);
                Bs[(c4+2) * LDS_ + kr] = f2tf(rB[p].z);
                Bs[(c4+3) * LDS_ + kr] = f2tf(rB[p].w);
            }
        }
    };
    // --- compute one BK=32 slice from buffer ---
    auto compute = [&](int buf) {
        const uint32_t* As = smu + buf * BUF_U;
        const uint32_t* Bs = As + TILE_U;
        #pragma unroll
        for (int ks = 0; ks < 4; ks++) {
            int kc = ks * 8;
            uint32_t a[4][4], b[4][2];
            #pragma unroll
            for (int mt = 0; mt < 4; mt++) {
                int rb = wm * 64 + mt * 16;
                const uint32_t* p0 = As + (rb + gq) * LDS_ + kc + tg;
                const uint32_t* p1 = As + (rb + gq + 8) * LDS_ + kc + tg;
                a[mt][0] = p0[0]; a[mt][2] = p0[4];
                a[mt][1] = p1[0]; a[mt][3] = p1[4];
            }
            #pragma unroll
            for (int nt = 0; nt < 4; nt++) {
                int cb = wn * 32 + nt * 8;
                const uint32_t* pb = Bs + (cb + gq) * LDS_ + kc + tg;
                b[nt][0] = pb[0]; b[nt][1] = pb[4];
            }
            #pragma unroll
            for (int mt = 0; mt < 4; mt++)
                #pragma unroll
                for (int nt = 0; nt < 4; nt++)
                    mma8(acc[mt][nt], a[mt], b[nt]);
        }
    };

    // --- pipelined mainloop (register-prefetch double buffer) ---
    loadA(0); loadB(0);
    store(0);
    __syncthreads();
    for (int it = 0; it < niter; ++it) {
        if (it + 1 < niter) { loadA((it+1)*BKT); loadB((it+1)*BKT); }
        compute(it & 1);
        if (it + 1 < niter) {
            store((it + 1) & 1);
            __syncthreads();
        }
    }

    // --- epilogue ---
    #pragma unroll
    for (int mt = 0; mt < 4; mt++) {
        int row = m0 + wm * 64 + mt * 16 + gq;
        #pragma unroll
        for (int nt = 0; nt < 4; nt++) {
            int col = n0 + wn * 32 + nt * 8 + 2 * tg;
            float b0 = 0.f, b1 = 0.f;
            if (BIAS) { b0 = bias[col]; b1 = bias[col + 1]; }
            float2 v0, v1;
            v0.x = acc[mt][nt][0] + b0; v0.y = acc[mt][nt][1] + b1;
            v1.x = acc[mt][nt][2] + b0; v1.y = acc[mt][nt][3] + b1;
            *(float2*)(C + (long)row * ldc + col)       = v0;
            *(float2*)(C + (long)(row + 8) * ldc + col) = v1;
        }
    }
}

// ---------------------------------------------------------------------------
// RoPE in-place on q,k
// ---------------------------------------------------------------------------
__global__ __launch_bounds__(256)
void rope_k(float* __restrict__ qkv)
{
    long t = (long)blockIdx.x * blockDim.x + threadIdx.x;
    int j = (int)(t & 63);
    int h = (int)((t >> 6) & (HH_-1));
    long bs = t >> 10;
    int s = (int)(bs & (SS-1));

    float inv = powf(10000.f, -((float)(2*j)) * (1.f/128.f));
    float fr  = (float)s * inv;
    float c, sn;
    sincosf(fr, &sn, &c);

    float* q = qkv + bs*(long)E3 + (long)h*DD;
    float q1 = q[j], q2 = q[j+64];
    q[j]    = q1*c - q2*sn;
    q[j+64] = q1*sn + q2*c;

    float* k = q + EE;
    float k1 = k[j], k2 = k[j+64];
    k[j]    = k1*c - k2*sn;
    k[j+64] = k1*sn + k2*c;
}

// ---------------------------------------------------------------------------
// Causal softmax; zeros masked region only up to the row's 128-block end
// (P@V limits K to m0+128, so nothing past that is ever read).
// ---------------------------------------------------------------------------
__global__ __launch_bounds__(256)
void softmax_k(float* __restrict__ p, float scale)
{
    const int S = SS;
    int s = blockIdx.x;
    long base = (long)blockIdx.y * S * S + (long)s * S;
    int n = s + 1;
    int tid = threadIdx.x;

    __shared__ float red[256];
    float ev[8];
    int cnt = 0;
    float mx = -3.4e38f;
    for (int i = tid; i < n; i += 256) {
        float v = p[base + i] * scale;
        ev[cnt++] = v;
        mx = fmaxf(mx, v);
    }
    red[tid] = mx; __syncthreads();
    for (int off = 128; off; off >>= 1) {
        if (tid < off) red[tid] = fmaxf(red[tid], red[tid + off]);
        __syncthreads();
    }
    mx = red[0]; __syncthreads();

    float sum = 0.f;
    for (int c = 0; c < cnt; c++) { ev[c] = expf(ev[c] - mx); sum += ev[c]; }
    red[tid] = sum; __syncthreads();
    for (int off = 128; off; off >>= 1) {
        if (tid < off) red[tid] += red[tid + off];
        __syncthreads();
    }
    float invs = 1.f / red[0];

    cnt = 0;
    for (int i = tid; i < n; i += 256) p[base + i] = ev[cnt++] * invs;
    int kz = min(S, ((s >> 7) + 1) << 7);
    for (int i = n + tid; i < kz; i += 256) p[base + i] = 0.f;
}

// ---------------------------------------------------------------------------
extern "C" void kernel_launch(void* const* d_in, const int* in_sizes, int n_in,
                              void* d_out, int out_size)
{
    const float* x      = (const float*)d_in[0];
    const float* wqkv_w = (const float*)d_in[1];
    const float* wqkv_b = (const float*)d_in[2];
    const float* out_w  = (const float*)d_in[3];
    const float* out_b  = (const float*)d_in[4];
    float*       out    = (float*)d_out;

    float *qkv, *sc, *ctx;
    cudaGetSymbolAddress((void**)&qkv, g_qkv);
    cudaGetSymbolAddress((void**)&sc,  g_sc);
    cudaGetSymbolAddress((void**)&ctx, g_ctx);

    cudaFuncSetAttribute(tgemm<true,true,0>,  cudaFuncAttributeMaxDynamicSharedMemorySize, SMEM_SZ);
    cudaFuncSetAttribute(tgemm<true,false,1>, cudaFuncAttributeMaxDynamicSharedMemorySize, SMEM_SZ);
    cudaFuncSetAttribute(tgemm<false,false,2>,cudaFuncAttributeMaxDynamicSharedMemorySize, SMEM_SZ);

    const int Mx = BB*SS;             // 4096
    const long sQKVb = (long)SS*E3;
    const long sSCb  = (long)HH_*SS*SS;
    const long sSCh  = (long)SS*SS;

    // 1) QKV projection: [4096,2048] @ [6144,2048]^T + bias
    {
        dim3 g(E3/BN, Mx/BM, 1);
        tgemm<true,true,0><<<g,256,SMEM_SZ>>>(x, wqkv_w, qkv, wqkv_b,
            Mx, E3, EE, EE, EE, E3, 0,0,0,0,0,0, 1);
    }
    // 2) RoPE
    {
        long total = (long)BB*SS*HH_*64;
        rope_k<<<(unsigned)(total/256), 256>>>(qkv);
    }
    // 3) scores = q @ k^T (causal tile skip)
    {
        dim3 g(SS/BN, SS/BM, BB*HH_);
        tgemm<true,false,1><<<g,256,SMEM_SZ>>>(qkv, qkv + EE, sc, nullptr,
            SS, SS, DD, E3, E3, SS,
            sQKVb, DD, sQKVb, DD, sSCb, sSCh, HH_);
    }
    // 4) softmax
    {
        float scale = 1.f / sqrtf((float)DD);
        softmax_k<<<dim3(SS, BB*HH_), 256>>>(sc, scale);
    }
    // 5) ctx = probs @ v (K limited by causality)
    {
        dim3 g(DD/BN, SS/BM, BB*HH_);
        tgemm<false,false,2><<<g,256,SMEM_SZ>>>(sc, qkv + 2*EE, ctx, nullptr,
            SS, DD, SS, SS, E3, EE,
            sSCb, sSCh, sQKVb, DD, (long)SS*EE, DD, HH_);
    }
    // 6) output projection
    {
        dim3 g(EE/BN, Mx/BM, 1);
        tgemm<true,true,0><<<g,256,SMEM_SZ>>>(ctx, out_w, out, out_b,
            Mx, EE, EE, EE, EE, EE, 0,0,0,0,0,0, 1);
    }
}

// round 4
// speedup vs baseline: 2.7061x; 1.0758x over previous
#include <cuda_runtime.h>
#include <math.h>
#include <cstdint>

// Problem constants
#define BB 2
#define SS 2048
#define EE 2048
#define HH_ 16
#define DD 128
#define E3 (3*EE)

// Scratch (allocation-free rule: __device__ globals)
__device__ float g_qkv[(long)BB*SS*E3];        //  96 MB
__device__ float g_sc [(long)BB*HH_*SS*SS];    // 512 MB
__device__ float g_ctx[(long)BB*SS*EE];        //  32 MB

__device__ __forceinline__ uint32_t f2tf(float f) {
    uint32_t r; asm("cvt.rna.tf32.f32 %0, %1;" : "=r"(r) : "f"(f)); return r;
}
__device__ __forceinline__ void mma8(float* d, const uint32_t* a, const uint32_t* b) {
    asm volatile("mma.sync.aligned.m16n8k8.row.col.f32.tf32.tf32.f32 "
        "{%0,%1,%2,%3}, {%4,%5,%6,%7}, {%8,%9}, {%0,%1,%2,%3};"
        : "+f"(d[0]), "+f"(d[1]), "+f"(d[2]), "+f"(d[3])
        : "r"(a[0]), "r"(a[1]), "r"(a[2]), "r"(a[3]), "r"(b[0]), "r"(b[1]));
}
__device__ __forceinline__ uint32_t smem_u32(const void* p) {
    uint32_t a;
    asm("{ .reg .u64 t; cvta.to.shared.u64 t, %1; cvt.u32.u64 %0, t; }"
        : "=r"(a) : "l"(p));
    return a;
}
#define CP_ASYNC16(dst, src) \
    asm volatile("cp.async.ca.shared.global [%0], [%1], 16;" :: "r"(dst), "l"(src))
#define CP_COMMIT() asm volatile("cp.async.commit_group;" ::: "memory")
#define CP_WAIT(n)  asm volatile("cp.async.wait_group %0;" :: "n"(n) : "memory")

// ===========================================================================
// NEW pipelined GEMM (TRANSB only): C[m,n]= sum_k A[m,k]*B[n,k] (+bias)
// CTA tile 128x256, 8 warps (2x4), warp tile 64x64, BK=32, 3-stage cp.async.
// fp32 in smem (stride 36), cvt->tf32 at fragment load.
// ===========================================================================
#define BM2 128
#define BN2 256
#define BKT 32
#define LDP 36
#define A_ST (128*LDP)             // 4608 floats
#define B_ST (256*LDP)             // 9216 floats
#define ST_U (A_ST + B_ST)         // 13824 floats per stage
#define SMEM2 (3*ST_U*4)           // 165888 bytes

template<bool BIAS, bool CAUSAL>
__global__ __launch_bounds__(256)
void tgemm2(const float* __restrict__ gA, const float* __restrict__ gB,
            float* __restrict__ gC, const float* __restrict__ bias,
            int K, int lda, int ldb, int ldc,
            long sAb, long sAh, long sBb, long sBh, long sCb, long sCh, int HHd)
{
    extern __shared__ float smf[];
    int z = blockIdx.z, zb = z / HHd, zh = z % HHd;
    const float* A = gA + zb*sAb + zh*sAh;
    const float* B = gB + zb*sBb + zh*sBh;
    float*       C = gC + zb*sCb + zh*sCh;

    int m0 = blockIdx.y * BM2;
    int n0 = blockIdx.x * BN2;
    if (CAUSAL && n0 > m0 + BM2 - 1) return;
    int niter = K / BKT;

    int tid  = threadIdx.x;
    int wid  = tid >> 5;
    int lane = tid & 31;
    int wm = wid & 1;              // 0..1 : 64-row slab
    int wn = wid >> 1;             // 0..3 : 64-col slab
    int gq = lane >> 2;            // 0..7
    int tg = lane & 3;             // 0..3

    float acc[4][8][4];
    #pragma unroll
    for (int mt = 0; mt < 4; mt++)
        #pragma unroll
        for (int nt = 0; nt < 8; nt++)
            #pragma unroll
            for (int r = 0; r < 4; r++) acc[mt][nt][r] = 0.f;

    auto issue = [&](int it) {
        int k0 = it * BKT;
        float* As = smf + (it % 3) * ST_U;
        float* Bs = As + A_ST;
        const float* Ab = A + (long)m0 * lda + k0;
        #pragma unroll
        for (int p = 0; p < 4; p++) {
            int idx = p * 256 + tid;
            int r = idx >> 3, c4 = (idx & 7) << 2;
            CP_ASYNC16(smem_u32(As + r * LDP + c4), Ab + (long)r * lda + c4);
        }
        const float* Bb = B + (long)n0 * ldb + k0;
        #pragma unroll
        for (int p = 0; p < 8; p++) {
            int idx = p * 256 + tid;
            int r = idx >> 3, c4 = (idx & 7) << 2;
            CP_ASYNC16(smem_u32(Bs + r * LDP + c4), Bb + (long)r * ldb + c4);
        }
        CP_COMMIT();
    };

    auto compute = [&](int s) {
        const float* As = smf + s * ST_U;
        const float* Bs = As + A_ST;
        #pragma unroll
        for (int ks = 0; ks < 4; ks++) {
            int kc = ks * 8;
            uint32_t a[4][4], b[8][2];
            #pragma unroll
            for (int mt = 0; mt < 4; mt++) {
                const float* p0 = As + (wm*64 + mt*16 + gq) * LDP + kc + tg;
                const float* p1 = p0 + 8 * LDP;
                a[mt][0] = f2tf(p0[0]); a[mt][2] = f2tf(p0[4]);
                a[mt][1] = f2tf(p1[0]); a[mt][3] = f2tf(p1[4]);
            }
            #pragma unroll
            for (int nt = 0; nt < 8; nt++) {
                const float* pb = Bs + (wn*64 + nt*8 + gq) * LDP + kc + tg;
                b[nt][0] = f2tf(pb[0]); b[nt][1] = f2tf(pb[4]);
            }
            #pragma unroll
            for (int mt = 0; mt < 4; mt++)
                #pragma unroll
                for (int nt = 0; nt < 8; nt++)
                    mma8(acc[mt][nt], a[mt], b[nt]);
        }
    };

    issue(0);
    if (niter > 1) issue(1);
    for (int it = 0; it < niter; ++it) {
        if (it + 1 < niter) CP_WAIT(1); else CP_WAIT(0);
        __syncthreads();
        if (it + 2 < niter) issue(it + 2);
        compute(it % 3);
        __syncthreads();
    }

    // epilogue
    #pragma unroll
    for (int mt = 0; mt < 4; mt++) {
        int row = m0 + wm*64 + mt*16 + gq;
        #pragma unroll
        for (int nt = 0; nt < 8; nt++) {
            int col = n0 + wn*64 + nt*8 + 2*tg;
            float b0 = 0.f, b1 = 0.f;
            if (BIAS) { b0 = bias[col]; b1 = bias[col + 1]; }
            float2 v0, v1;
            v0.x = acc[mt][nt][0] + b0; v0.y = acc[mt][nt][1] + b1;
            v1.x = acc[mt][nt][2] + b0; v1.y = acc[mt][nt][3] + b1;
            *(float2*)(C + (long)row * ldc + col)       = v0;
            *(float2*)(C + (long)(row + 8) * ldc + col) = v1;
        }
    }
}

// ===========================================================================
// R3 GEMM kept for P@V (TRANSB=false, CAUSAL==2 K-limit, N=128)
// ===========================================================================
#define BM 128
#define BN 128
#define LDS_ 36
#define TILE_U (128*LDS_)
#define BUF_U  (2*TILE_U)
#define SMEM_SZ (2*BUF_U*4)

template<bool TRANSB, bool BIAS, int CAUSAL>
__global__ __launch_bounds__(256)
void tgemm(const float* __restrict__ gA, const float* __restrict__ gB,
           float* __restrict__ gC, const float* __restrict__ bias,
           int M, int N, int K, int lda, int ldb, int ldc,
           long sAb, long sAh, long sBb, long sBh, long sCb, long sCh, int HHd)
{
    extern __shared__ uint32_t smu[];
    int z = blockIdx.z, zb = z / HHd, zh = z % HHd;
    const float* A = gA + zb*sAb + zh*sAh;
    const float* B = gB + zb*sBb + zh*sBh;
    float*       C = gC + zb*sCb + zh*sCh;

    int m0 = blockIdx.y * BM;
    int n0 = blockIdx.x * BN;
    if (CAUSAL == 1 && n0 > m0 + BM - 1) return;
    int Kend = (CAUSAL == 2) ? min(K, m0 + BM) : K;
    int niter = Kend / BKT;

    int tid  = threadIdx.x;
    int wid  = tid >> 5;
    int lane = tid & 31;
    int wm = wid & 1;
    int wn = wid >> 1;
    int gq = lane >> 2;
    int tg = lane & 3;

    float acc[4][4][4];
    #pragma unroll
    for (int mt = 0; mt < 4; mt++)
        #pragma unroll
        for (int nt = 0; nt < 4; nt++)
            #pragma unroll
            for (int r = 0; r < 4; r++) acc[mt][nt][r] = 0.f;

    float4 rA[4], rB[4];

    auto loadA = [&](int k0) {
        const float* Ab = A + (long)m0 * lda + k0;
        #pragma unroll
        for (int p = 0; p < 4; p++) {
            int idx = p * 256 + tid;
            int row = idx >> 3, c4 = (idx & 7) << 2;
            rA[p] = *(const float4*)(Ab + (long)row * lda + c4);
        }
    };
    auto loadB = [&](int k0) {
        if (TRANSB) {
            const float* Bb = B + (long)n0 * ldb + k0;
            #pragma unroll
            for (int p = 0; p < 4; p++) {
                int idx = p * 256 + tid;
                int row = idx >> 3, c4 = (idx & 7) << 2;
                rB[p] = *(const float4*)(Bb + (long)row * ldb + c4);
            }
        } else {
            const float* Bb = B + (long)k0 * ldb + n0;
            #pragma unroll
            for (int p = 0; p < 4; p++) {
                int idx = p * 256 + tid;
                int kr = idx >> 5, c4 = (idx & 31) << 2;
                rB[p] = *(const float4*)(Bb + (long)kr * ldb + c4);
            }
        }
    };
    auto store = [&](int buf) {
        uint32_t* As = smu + buf * BUF_U;
        uint32_t* Bs = As + TILE_U;
        #pragma unroll
        for (int p = 0; p < 4; p++) {
            int idx = p * 256 + tid;
            int row = idx >> 3, c4 = (idx & 7) << 2;
            uint32_t* d = As + row * LDS_ + c4;
            d[0] = f2tf(rA[p].x); d[1] = f2tf(rA[p].y);
            d[2] = f2tf(rA[p].z); d[3] = f2tf(rA[p].w);
        }
        if (TRANSB) {
            #pragma unroll
            for (int p = 0; p < 4; p++) {
                int idx = p * 256 + tid;
                int row = idx >> 3, c4 = (idx & 7) << 2;
                uint32_t* d = Bs + row * LDS_ + c4;
                d[0] = f2tf(rB[p].x); d[1] = f2tf(rB[p].y);
                d[2] = f2tf(rB[p].z); d[3] = f2tf(rB[p].w);
            }
        } else {
            #pragma unroll
            for (int p = 0; p < 4; p++) {
                int idx = p * 256 + tid;
                int kr = idx >> 5, c4 = (idx & 31) << 2;
                Bs[(c4+0) * LDS_ + kr] = f2tf(rB[p].x);
                Bs[(c4+1) * LDS_ + kr] = f2tf(rB[p].y);
                Bs[(c4+2) * LDS_ + kr] = f2tf(rB[p].z);
                Bs[(c4+3) * LDS_ + kr] = f2tf(rB[p].w);
            }
        }
    };
    auto compute = [&](int buf) {
        const uint32_t* As = smu + buf * BUF_U;
        const uint32_t* Bs = As + TILE_U;
        #pragma unroll
        for (int ks = 0; ks < 4; ks++) {
            int kc = ks * 8;
            uint32_t a[4][4], b[4][2];
            #pragma unroll
            for (int mt = 0; mt < 4; mt++) {
                int rb = wm * 64 + mt * 16;
                const uint32_t* p0 = As + (rb + gq) * LDS_ + kc + tg;
                const uint32_t* p1 = As + (rb + gq + 8) * LDS_ + kc + tg;
                a[mt][0] = p0[0]; a[mt][2] = p0[4];
                a[mt][1] = p1[0]; a[mt][3] = p1[4];
            }
            #pragma unroll
            for (int nt = 0; nt < 4; nt++) {
                int cb = wn * 32 + nt * 8;
                const uint32_t* pb = Bs + (cb + gq) * LDS_ + kc + tg;
                b[nt][0] = pb[0]; b[nt][1] = pb[4];
            }
            #pragma unroll
            for (int mt = 0; mt < 4; mt++)
                #pragma unroll
                for (int nt = 0; nt < 4; nt++)
                    mma8(acc[mt][nt], a[mt], b[nt]);
        }
    };

    loadA(0); loadB(0);
    store(0);
    __syncthreads();
    for (int it = 0; it < niter; ++it) {
        if (it + 1 < niter) { loadA((it+1)*BKT); loadB((it+1)*BKT); }
        compute(it & 1);
        if (it + 1 < niter) {
            store((it + 1) & 1);
            __syncthreads();
        }
    }

    #pragma unroll
    for (int mt = 0; mt < 4; mt++) {
        int row = m0 + wm * 64 + mt * 16 + gq;
        #pragma unroll
        for (int nt = 0; nt < 4; nt++) {
            int col = n0 + wn * 32 + nt * 8 + 2 * tg;
            float b0 = 0.f, b1 = 0.f;
            if (BIAS) { b0 = bias[col]; b1 = bias[col + 1]; }
            float2 v0, v1;
            v0.x = acc[mt][nt][0] + b0; v0.y = acc[mt][nt][1] + b1;
            v1.x = acc[mt][nt][2] + b0; v1.y = acc[mt][nt][3] + b1;
            *(float2*)(C + (long)row * ldc + col)       = v0;
            *(float2*)(C + (long)(row + 8) * ldc + col) = v1;
        }
    }
}

// ---------------------------------------------------------------------------
// RoPE in-place on q,k
// ---------------------------------------------------------------------------
__global__ __launch_bounds__(256)
void rope_k(float* __restrict__ qkv)
{
    long t = (long)blockIdx.x * blockDim.x + threadIdx.x;
    int j = (int)(t & 63);
    int h = (int)((t >> 6) & (HH_-1));
    long bs = t >> 10;
    int s = (int)(bs & (SS-1));

    float inv = powf(10000.f, -((float)(2*j)) * (1.f/128.f));
    float fr  = (float)s * inv;
    float c, sn;
    sincosf(fr, &sn, &c);

    float* q = qkv + bs*(long)E3 + (long)h*DD;
    float q1 = q[j], q2 = q[j+64];
    q[j]    = q1*c - q2*sn;
    q[j+64] = q1*sn + q2*c;

    float* k = q + EE;
    float k1 = k[j], k2 = k[j+64];
    k[j]    = k1*c - k2*sn;
    k[j+64] = k1*sn + k2*c;
}

// ---------------------------------------------------------------------------
// Causal softmax; zeros masked region only up to the row's 128-block end
// ---------------------------------------------------------------------------
__global__ __launch_bounds__(256)
void softmax_k(float* __restrict__ p, float scale)
{
    const int S = SS;
    int s = blockIdx.x;
    long base = (long)blockIdx.y * S * S + (long)s * S;
    int n = s + 1;
    int tid = threadIdx.x;

    __shared__ float red[256];
    float ev[8];
    int cnt = 0;
    float mx = -3.4e38f;
    for (int i = tid; i < n; i += 256) {
        float v = p[base + i] * scale;
        ev[cnt++] = v;
        mx = fmaxf(mx, v);
    }
    red[tid] = mx; __syncthreads();
    for (int off = 128; off; off >>= 1) {
        if (tid < off) red[tid] = fmaxf(red[tid], red[tid + off]);
        __syncthreads();
    }
    mx = red[0]; __syncthreads();

    float sum = 0.f;
    for (int c = 0; c < cnt; c++) { ev[c] = expf(ev[c] - mx); sum += ev[c]; }
    red[tid] = sum; __syncthreads();
    for (int off = 128; off; off >>= 1) {
        if (tid < off) red[tid] += red[tid + off];
        __syncthreads();
    }
    float invs = 1.f / red[0];

    cnt = 0;
    for (int i = tid; i < n; i += 256) p[base + i] = ev[cnt++] * invs;
    int kz = min(S, ((s >> 7) + 1) << 7);
    for (int i = n + tid; i < kz; i += 256) p[base + i] = 0.f;
}

// ---------------------------------------------------------------------------
extern "C" void kernel_launch(void* const* d_in, const int* in_sizes, int n_in,
                              void* d_out, int out_size)
{
    const float* x      = (const float*)d_in[0];
    const float* wqkv_w = (const float*)d_in[1];
    const float* wqkv_b = (const float*)d_in[2];
    const float* out_w  = (const float*)d_in[3];
    const float* out_b  = (const float*)d_in[4];
    float*       out    = (float*)d_out;

    float *qkv, *sc, *ctx;
    cudaGetSymbolAddress((void**)&qkv, g_qkv);
    cudaGetSymbolAddress((void**)&sc,  g_sc);
    cudaGetSymbolAddress((void**)&ctx, g_ctx);

    cudaFuncSetAttribute(tgemm2<true,false>,  cudaFuncAttributeMaxDynamicSharedMemorySize, SMEM2);
    cudaFuncSetAttribute(tgemm2<false,true>,  cudaFuncAttributeMaxDynamicSharedMemorySize, SMEM2);
    cudaFuncSetAttribute(tgemm<false,false,2>,cudaFuncAttributeMaxDynamicSharedMemorySize, SMEM_SZ);

    const int Mx = BB*SS;             // 4096
    const long sQKVb = (long)SS*E3;
    const long sSCb  = (long)HH_*SS*SS;
    const long sSCh  = (long)SS*SS;

    // 1) QKV projection: [4096,2048] @ [6144,2048]^T + bias
    {
        dim3 g(E3/BN2, Mx/BM2, 1);
        tgemm2<true,false><<<g,256,SMEM2>>>(x, wqkv_w, qkv, wqkv_b,
            EE, EE, EE, E3, 0,0,0,0,0,0, 1);
    }
    // 2) RoPE
    {
        long total = (long)BB*SS*HH_*64;
        rope_k<<<(unsigned)(total/256), 256>>>(qkv);
    }
    // 3) scores = q @ k^T (causal tile skip)
    {
        dim3 g(SS/BN2, SS/BM2, BB*HH_);
        tgemm2<false,true><<<g,256,SMEM2>>>(qkv, qkv + EE, sc, nullptr,
            DD, E3, E3, SS,
            sQKVb, DD, sQKVb, DD, sSCb, sSCh, HH_);
    }
    // 4) softmax
    {
        float scale = 1.f / sqrtf((float)DD);
        softmax_k<<<dim3(SS, BB*HH_), 256>>>(sc, scale);
    }
    // 5) ctx = probs @ v (K limited by causality) — R3 kernel
    {
        dim3 g(DD/BN, SS/BM, BB*HH_);
        tgemm<false,false,2><<<g,256,SMEM_SZ>>>(sc, qkv + 2*EE, ctx, nullptr,
            SS, DD, SS, SS, E3, EE,
            sSCb, sSCh, sQKVb, DD, (long)SS*EE, DD, HH_);
    }
    // 6) output projection
    {
        dim3 g(EE/BN2, Mx/BM2, 1);
        tgemm2<true,false><<<g,256,SMEM2>>>(ctx, out_w, out, out_b,
            EE, EE, EE, EE, 0,0,0,0,0,0, 1);
    }
}

// round 5
// speedup vs baseline: 3.3474x; 1.2370x over previous
#include <cuda_runtime.h>
#include <math.h>
#include <cstdint>

// Problem constants
#define BB 2
#define SS 2048
#define EE 2048
#define HH_ 16
#define DD 128
#define E3 (3*EE)

// Scratch (allocation-free rule: __device__ globals)
__device__ float g_qkv[(long)BB*SS*E3];        //  96 MB
__device__ float g_ctx[(long)BB*SS*EE];        //  32 MB

__device__ __forceinline__ uint32_t f2tf(float f) {
    uint32_t r; asm("cvt.rna.tf32.f32 %0, %1;" : "=r"(r) : "f"(f)); return r;
}
__device__ __forceinline__ void mma8(float* d, const uint32_t* a, const uint32_t* b) {
    asm volatile("mma.sync.aligned.m16n8k8.row.col.f32.tf32.tf32.f32 "
        "{%0,%1,%2,%3}, {%4,%5,%6,%7}, {%8,%9}, {%0,%1,%2,%3};"
        : "+f"(d[0]), "+f"(d[1]), "+f"(d[2]), "+f"(d[3])
        : "r"(a[0]), "r"(a[1]), "r"(a[2]), "r"(a[3]), "r"(b[0]), "r"(b[1]));
}
__device__ __forceinline__ uint32_t smem_u32(const void* p) {
    uint32_t a;
    asm("{ .reg .u64 t; cvta.to.shared.u64 t, %1; cvt.u32.u64 %0, t; }"
        : "=r"(a) : "l"(p));
    return a;
}
#define CP_ASYNC16(dst, src) \
    asm volatile("cp.async.ca.shared.global [%0], [%1], 16;" :: "r"(dst), "l"(src))
#define CP_COMMIT() asm volatile("cp.async.commit_group;" ::: "memory")
#define CP_WAIT(n)  asm volatile("cp.async.wait_group %0;" :: "n"(n) : "memory")

// ===========================================================================
// Pipelined GEMM (TRANSB): C[m,n]= sum_k A[m,k]*B[n,k] (+bias)
// CTA tile 128x256, 8 warps (2x4), warp tile 64x64, BK=32, 3-stage cp.async.
// ===========================================================================
#define BM2 128
#define BN2 256
#define BKT 32
#define LDP 36
#define A_ST (128*LDP)
#define B_ST (256*LDP)
#define ST_U (A_ST + B_ST)
#define SMEM2 (3*ST_U*4)           // 165888 bytes

template<bool BIAS>
__global__ __launch_bounds__(256)
void tgemm2(const float* __restrict__ gA, const float* __restrict__ gB,
            float* __restrict__ gC, const float* __restrict__ bias,
            int K, int lda, int ldb, int ldc)
{
    extern __shared__ float smf[];
    const float* A = gA;
    const float* B = gB;
    float*       C = gC;

    int m0 = blockIdx.y * BM2;
    int n0 = blockIdx.x * BN2;
    int niter = K / BKT;

    int tid  = threadIdx.x;
    int wid  = tid >> 5;
    int lane = tid & 31;
    int wm = wid & 1;
    int wn = wid >> 1;
    int gq = lane >> 2;
    int tg = lane & 3;

    float acc[4][8][4];
    #pragma unroll
    for (int mt = 0; mt < 4; mt++)
        #pragma unroll
        for (int nt = 0; nt < 8; nt++)
            #pragma unroll
            for (int r = 0; r < 4; r++) acc[mt][nt][r] = 0.f;

    auto issue = [&](int it) {
        int k0 = it * BKT;
        float* As = smf + (it % 3) * ST_U;
        float* Bs = As + A_ST;
        const float* Ab = A + (long)m0 * lda + k0;
        #pragma unroll
        for (int p = 0; p < 4; p++) {
            int idx = p * 256 + tid;
            int r = idx >> 3, c4 = (idx & 7) << 2;
            CP_ASYNC16(smem_u32(As + r * LDP + c4), Ab + (long)r * lda + c4);
        }
        const float* Bb = B + (long)n0 * ldb + k0;
        #pragma unroll
        for (int p = 0; p < 8; p++) {
            int idx = p * 256 + tid;
            int r = idx >> 3, c4 = (idx & 7) << 2;
            CP_ASYNC16(smem_u32(Bs + r * LDP + c4), Bb + (long)r * ldb + c4);
        }
        CP_COMMIT();
    };

    auto compute = [&](int s) {
        const float* As = smf + s * ST_U;
        const float* Bs = As + A_ST;
        #pragma unroll
        for (int ks = 0; ks < 4; ks++) {
            int kc = ks * 8;
            uint32_t a[4][4], b[8][2];
            #pragma unroll
            for (int mt = 0; mt < 4; mt++) {
                const float* p0 = As + (wm*64 + mt*16 + gq) * LDP + kc + tg;
                const float* p1 = p0 + 8 * LDP;
                a[mt][0] = f2tf(p0[0]); a[mt][2] = f2tf(p0[4]);
                a[mt][1] = f2tf(p1[0]); a[mt][3] = f2tf(p1[4]);
            }
            #pragma unroll
            for (int nt = 0; nt < 8; nt++) {
                const float* pb = Bs + (wn*64 + nt*8 + gq) * LDP + kc + tg;
                b[nt][0] = f2tf(pb[0]); b[nt][1] = f2tf(pb[4]);
            }
            #pragma unroll
            for (int mt = 0; mt < 4; mt++)
                #pragma unroll
                for (int nt = 0; nt < 8; nt++)
                    mma8(acc[mt][nt], a[mt], b[nt]);
        }
    };

    issue(0);
    if (niter > 1) issue(1);
    for (int it = 0; it < niter; ++it) {
        if (it + 1 < niter) CP_WAIT(1); else CP_WAIT(0);
        __syncthreads();
        if (it + 2 < niter) issue(it + 2);
        compute(it % 3);
        __syncthreads();
    }

    #pragma unroll
    for (int mt = 0; mt < 4; mt++) {
        int row = m0 + wm*64 + mt*16 + gq;
        #pragma unroll
        for (int nt = 0; nt < 8; nt++) {
            int col = n0 + wn*64 + nt*8 + 2*tg;
            float b0 = 0.f, b1 = 0.f;
            if (BIAS) { b0 = bias[col]; b1 = bias[col + 1]; }
            float2 v0, v1;
            v0.x = acc[mt][nt][0] + b0; v0.y = acc[mt][nt][1] + b1;
            v1.x = acc[mt][nt][2] + b0; v1.y = acc[mt][nt][3] + b1;
            *(float2*)(C + (long)row * ldc + col)       = v0;
            *(float2*)(C + (long)(row + 8) * ldc + col) = v1;
        }
    }
}

// ===========================================================================
// Flash attention: per CTA one 128-row q-tile of one (b,h).
// 8 warps x 16 rows; K/V tiles of 64 rows; online softmax; O in regs.
// Smem (floats/u32): Q[128][132] tf32 | K[64][132] f32 | V[64][136] f32 |
//                    P[128][68] tf32      = 171,008 bytes
// ===========================================================================
#define FQ_LD 132
#define FV_LD 136
#define FP_LD 68
#define FA_Q_U   (128*FQ_LD)
#define FA_K_U   (64*FQ_LD)
#define FA_V_U   (64*FV_LD)
#define FA_P_U   (128*FP_LD)
#define FA_SMEM  ((FA_Q_U + FA_K_U + FA_V_U + FA_P_U)*4)

__global__ __launch_bounds__(256)
void fa_k(const float* __restrict__ qkv, float* __restrict__ ctx)
{
    extern __shared__ uint32_t sm[];
    uint32_t* Qs = sm;
    float*    Ks = (float*)(sm + FA_Q_U);
    float*    Vs = Ks + FA_K_U;
    uint32_t* Ps = (uint32_t*)(Vs + FA_V_U);

    int qt = gridDim.x - 1 - blockIdx.x;       // heavy tiles first
    int bh = blockIdx.y;
    int b = bh >> 4, h = bh & 15;
    const float* qb = qkv + (long)b*SS*E3 + (long)h*DD;

    int tid = threadIdx.x, wid = tid >> 5, lane = tid & 31;
    int gq = lane >> 2, tg = lane & 3;

    // load Q tile (128 x 128) -> tf32 smem
    {
        const float* Qg = qb + (long)(qt*128)*E3;
        #pragma unroll
        for (int p = 0; p < 16; p++) {
            int idx = p*256 + tid;
            int r = idx >> 5, c4 = (idx & 31) << 2;
            float4 v = *(const float4*)(Qg + (long)r*E3 + c4);
            uint32_t* d = Qs + r*FQ_LD + c4;
            d[0]=f2tf(v.x); d[1]=f2tf(v.y); d[2]=f2tf(v.z); d[3]=f2tf(v.w);
        }
    }

    float o[16][4];
    #pragma unroll
    for (int nt = 0; nt < 16; nt++)
        #pragma unroll
        for (int r = 0; r < 4; r++) o[nt][r] = 0.f;
    float m0 = -1e30f, m1 = -1e30f, l0 = 0.f, l1 = 0.f;

    const float scale = 0.08838834764831845f;  // 1/sqrt(128)
    int rowg0 = qt*128 + wid*16 + gq;
    int rowg1 = rowg0 + 8;
    int nkt = 2*(qt + 1);

    for (int kt = 0; kt < nkt; kt++) {
        // ---- load K,V 64-row tiles ----
        const float* Kg = qb + EE   + (long)(kt*64)*E3;
        const float* Vg = qb + 2*EE + (long)(kt*64)*E3;
        #pragma unroll
        for (int p = 0; p < 8; p++) {
            int idx = p*256 + tid;
            int r = idx >> 5, c4 = (idx & 31) << 2;
            CP_ASYNC16(smem_u32(Ks + r*FQ_LD + c4), Kg + (long)r*E3 + c4);
        }
        #pragma unroll
        for (int p = 0; p < 8; p++) {
            int idx = p*256 + tid;
            int r = idx >> 5, c4 = (idx & 31) << 2;
            CP_ASYNC16(smem_u32(Vs + r*FV_LD + c4), Vg + (long)r*E3 + c4);
        }
        CP_COMMIT(); CP_WAIT(0);
        __syncthreads();

        // ---- S = Q K^T (warp: 16 rows x 64 cols) ----
        float s[8][4];
        #pragma unroll
        for (int nt = 0; nt < 8; nt++)
            #pragma unroll
            for (int r = 0; r < 4; r++) s[nt][r] = 0.f;

        #pragma unroll
        for (int ks = 0; ks < 16; ks++) {
            int kc = ks*8;
            uint32_t a[4];
            const uint32_t* p0 = Qs + (wid*16 + gq)*FQ_LD + kc + tg;
            const uint32_t* p1 = p0 + 8*FQ_LD;
            a[0] = p0[0]; a[1] = p1[0]; a[2] = p0[4]; a[3] = p1[4];
            #pragma unroll
            for (int nt = 0; nt < 8; nt++) {
                const float* pb = Ks + (nt*8 + gq)*FQ_LD + kc + tg;
                uint32_t bb[2] = { f2tf(pb[0]), f2tf(pb[4]) };
                mma8(s[nt], a, bb);
            }
        }

        // ---- scale + causal mask ----
        if (kt >= 2*qt) {
            #pragma unroll
            for (int nt = 0; nt < 8; nt++) {
                int col = kt*64 + nt*8 + 2*tg;
                s[nt][0] = (col   > rowg0) ? -1e30f : s[nt][0]*scale;
                s[nt][1] = (col+1 > rowg0) ? -1e30f : s[nt][1]*scale;
                s[nt][2] = (col   > rowg1) ? -1e30f : s[nt][2]*scale;
                s[nt][3] = (col+1 > rowg1) ? -1e30f : s[nt][3]*scale;
            }
        } else {
            #pragma unroll
            for (int nt = 0; nt < 8; nt++)
                #pragma unroll
                for (int r = 0; r < 4; r++) s[nt][r] *= scale;
        }

        // ---- online softmax ----
        float mt0 = -1e30f, mt1 = -1e30f;
        #pragma unroll
        for (int nt = 0; nt < 8; nt++) {
            mt0 = fmaxf(mt0, fmaxf(s[nt][0], s[nt][1]));
            mt1 = fmaxf(mt1, fmaxf(s[nt][2], s[nt][3]));
        }
        mt0 = fmaxf(mt0, __shfl_xor_sync(0xffffffffu, mt0, 1));
        mt0 = fmaxf(mt0, __shfl_xor_sync(0xffffffffu, mt0, 2));
        mt1 = fmaxf(mt1, __shfl_xor_sync(0xffffffffu, mt1, 1));
        mt1 = fmaxf(mt1, __shfl_xor_sync(0xffffffffu, mt1, 2));

        float mn0 = fmaxf(m0, mt0), mn1 = fmaxf(m1, mt1);
        float c0 = __expf(m0 - mn0), c1 = __expf(m1 - mn1);

        float sum0 = 0.f, sum1 = 0.f;
        #pragma unroll
        for (int nt = 0; nt < 8; nt++) {
            s[nt][0] = __expf(s[nt][0] - mn0);
            s[nt][1] = __expf(s[nt][1] - mn0);
            s[nt][2] = __expf(s[nt][2] - mn1);
            s[nt][3] = __expf(s[nt][3] - mn1);
            sum0 += s[nt][0] + s[nt][1];
            sum1 += s[nt][2] + s[nt][3];
        }
        sum0 += __shfl_xor_sync(0xffffffffu, sum0, 1);
        sum0 += __shfl_xor_sync(0xffffffffu, sum0, 2);
        sum1 += __shfl_xor_sync(0xffffffffu, sum1, 1);
        sum1 += __shfl_xor_sync(0xffffffffu, sum1, 2);

        l0 = l0*c0 + sum0;  l1 = l1*c1 + sum1;
        m0 = mn0;           m1 = mn1;

        #pragma unroll
        for (int nt = 0; nt < 16; nt++) {
            o[nt][0] *= c0; o[nt][1] *= c0;
            o[nt][2] *= c1; o[nt][3] *= c1;
        }

        // ---- P (tf32) -> warp-private smem ----
        #pragma unroll
        for (int nt = 0; nt < 8; nt++) {
            int cb = nt*8 + 2*tg;
            uint2 v0 = make_uint2(f2tf(s[nt][0]), f2tf(s[nt][1]));
            uint2 v1 = make_uint2(f2tf(s[nt][2]), f2tf(s[nt][3]));
            *(uint2*)&Ps[(wid*16 + gq    )*FP_LD + cb] = v0;
            *(uint2*)&Ps[(wid*16 + gq + 8)*FP_LD + cb] = v1;
        }
        __syncwarp();

        // ---- O += P @ V ----
        #pragma unroll
        for (int ks = 0; ks < 8; ks++) {
            int kc = ks*8;
            uint32_t a[4];
            const uint32_t* p0 = Ps + (wid*16 + gq)*FP_LD + kc + tg;
            const uint32_t* p1 = p0 + 8*FP_LD;
            a[0] = p0[0]; a[1] = p1[0]; a[2] = p0[4]; a[3] = p1[4];
            #pragma unroll
            for (int nt = 0; nt < 16; nt++) {
                const float* pv = Vs + (kc + tg)*FV_LD + nt*8 + gq;
                uint32_t bb[2] = { f2tf(pv[0]), f2tf(pv[4*FV_LD]) };
                mma8(o[nt], a, bb);
            }
        }
        __syncthreads();     // protect K/V before next iter's loads
    }

    // ---- normalize + store ----
    float i0 = 1.f/l0, i1 = 1.f/l1;
    float* cb0 = ctx + (long)b*SS*EE + (long)rowg0*EE + h*DD;
    float* cb1 = cb0 + 8*EE;
    #pragma unroll
    for (int nt = 0; nt < 16; nt++) {
        int col = nt*8 + 2*tg;
        float2 v0 = make_float2(o[nt][0]*i0, o[nt][1]*i0);
        float2 v1 = make_float2(o[nt][2]*i1, o[nt][3]*i1);
        *(float2*)(cb0 + col) = v0;
        *(float2*)(cb1 + col) = v1;
    }
}

// ---------------------------------------------------------------------------
// RoPE in-place on q,k
// ---------------------------------------------------------------------------
__global__ __launch_bounds__(256)
void rope_k(float* __restrict__ qkv)
{
    long t = (long)blockIdx.x * blockDim.x + threadIdx.x;
    int j = (int)(t & 63);
    int h = (int)((t >> 6) & (HH_-1));
    long bs = t >> 10;
    int s = (int)(bs & (SS-1));

    float inv = powf(10000.f, -((float)(2*j)) * (1.f/128.f));
    float fr  = (float)s * inv;
    float c, sn;
    sincosf(fr, &sn, &c);

    float* q = qkv + bs*(long)E3 + (long)h*DD;
    float q1 = q[j], q2 = q[j+64];
    q[j]    = q1*c - q2*sn;
    q[j+64] = q1*sn + q2*c;

    float* k = q + EE;
    float k1 = k[j], k2 = k[j+64];
    k[j]    = k1*c - k2*sn;
    k[j+64] = k1*sn + k2*c;
}

// ---------------------------------------------------------------------------
extern "C" void kernel_launch(void* const* d_in, const int* in_sizes, int n_in,
                              void* d_out, int out_size)
{
    const float* x      = (const float*)d_in[0];
    const float* wqkv_w = (const float*)d_in[1];
    const float* wqkv_b = (const float*)d_in[2];
    const float* out_w  = (const float*)d_in[3];
    const float* out_b  = (const float*)d_in[4];
    float*       out    = (float*)d_out;

    float *qkv, *ctx;
    cudaGetSymbolAddress((void**)&qkv, g_qkv);
    cudaGetSymbolAddress((void**)&ctx, g_ctx);

    cudaFuncSetAttribute(tgemm2<true>, cudaFuncAttributeMaxDynamicSharedMemorySize, SMEM2);
    cudaFuncSetAttribute(fa_k,         cudaFuncAttributeMaxDynamicSharedMemorySize, FA_SMEM);

    const int Mx = BB*SS;             // 4096

    // 1) QKV projection: [4096,2048] @ [6144,2048]^T + bias
    {
        dim3 g(E3/BN2, Mx/BM2, 1);
        tgemm2<true><<<g,256,SMEM2>>>(x, wqkv_w, qkv, wqkv_b, EE, EE, EE, E3);
    }
    // 2) RoPE
    {
        long total = (long)BB*SS*HH_*64;
        rope_k<<<(unsigned)(total/256), 256>>>(qkv);
    }
    // 3) fused flash attention -> ctx
    {
        dim3 g(SS/128, BB*HH_);
        fa_k<<<g,256,FA_SMEM>>>(qkv, ctx);
    }
    // 4) output projection
    {
        dim3 g(EE/BN2, Mx/BM2, 1);
        tgemm2<true><<<g,256,SMEM2>>>(ctx, out_w, out, out_b, EE, EE, EE, EE);
    }
}